// round 15
// baseline (speedup 1.0000x reference)
#include <cuda_runtime.h>
#include <cuda_fp16.h>
#include <math.h>

namespace {
constexpr int L   = 1024;
constexpr int D   = 1024;
constexpr int H   = 16;
constexpr int KVH = 8;
constexpr int HD  = 64;
constexpr int NS  = 128;
constexpr int DT  = 64;
constexpr int E   = 8;
constexpr int HID = 4096;
constexpr int PRJ = DT + 2*NS; // 320
constexpr int QKVN = 2048;
constexpr int BK  = 64;
constexpr int NSTG = 3;
constexpr int LDSH = BK + 8;   // 72 halves = 144B rows (conflict-free ldmatrix)
}

// ------------------ scratch: device globals ------------------
__device__ float  g_xn[L*D];
__device__ __half g_xnH[L*D];
__device__ __half g_snH[L*D];
__device__ __half g_snselH[L*D];
__device__ __half g_projH[L*PRJ];
__device__ __half g_deltaH[L*D];
__device__ __half g_pinH[3*L*D];   // slice0: ssm scan out, slice1: attn out, slice2: conv-silu
__device__ float  g_pout[3*L*D];   // batched projection outputs
__device__ __half g_wqkvH[QKVN*D];
__device__ __half g_qkvH[L*QKVN];
__device__ __half g_qrH[H*L*HD];
__device__ __half g_krH[H*L*HD];
__device__ __half g_vtH[H*HD*L];
__device__ __half g_scoresH[H*L*L];
__device__ float  g_sinv[H*L];
__device__ float  g_weights[L*4];
__device__ float  g_x2[L*D];
__device__ __half g_x2H[L*D];
__device__ float  g_vals[L*2];
__device__ int    g_topidx[L*2];
__device__ float  g_w0[L];
__device__ float  g_w1[L];
__device__ int    g_cnt[E];
__device__ int    g_tok[E*L];
__device__ int    g_slot[E*L];
__device__ __half g_hhH[(long long)E*L*HID];
__device__ __half g_yH [(long long)E*L*D];
__device__ float  g_moe[2*L*D];
// half weight shadows
__device__ __half g_selwH[D*D];
__device__ __half g_xpwH[PRJ*D];
__device__ __half g_dtwH[D*DT];
__device__ __half g_wprojH[3*D*D];  // slice0: ssm_out_w, slice1: o_w, slice2: pw_w
__device__ __half g_ew1H[(long long)E*2*HID*D];   // rows interleaved: 2j=a_j, 2j+1=g_j
__device__ __half g_ew2H[(long long)E*D*HID];
__device__ __half g_elwH[(long long)E*D*D];

__device__ __forceinline__ float warpSum(float v){
    #pragma unroll
    for (int o = 16; o; o >>= 1) v += __shfl_xor_sync(0xffffffffu, v, o);
    return v;
}

__device__ __forceinline__ void cp16(__half* smem, const __half* g, bool pred){
    unsigned s = (unsigned)__cvta_generic_to_shared(smem);
    int sz = pred ? 16 : 0;
    asm volatile("cp.async.cg.shared.global [%0], [%1], 16, %2;\n"
                 :: "r"(s), "l"(g), "r"(sz));
}
__device__ __forceinline__ void cpcommit(){ asm volatile("cp.async.commit_group;\n"); }
template<int N> __device__ __forceinline__ void cpwait(){ asm volatile("cp.async.wait_group %0;\n" :: "n"(N)); }

__device__ __forceinline__ void mma16(float* d, const unsigned* a, const unsigned* b){
    asm volatile(
      "mma.sync.aligned.m16n8k16.row.col.f32.f16.f16.f32 "
      "{%0,%1,%2,%3},{%4,%5,%6,%7},{%8,%9},{%0,%1,%2,%3};"
      : "+f"(d[0]), "+f"(d[1]), "+f"(d[2]), "+f"(d[3])
      : "r"(a[0]), "r"(a[1]), "r"(a[2]), "r"(a[3]), "r"(b[0]), "r"(b[1]));
}
__device__ __forceinline__ void ldsm4(unsigned* r, unsigned addr){
    asm volatile("ldmatrix.sync.aligned.m8n8.x4.shared.b16 {%0,%1,%2,%3}, [%4];"
                 : "=r"(r[0]), "=r"(r[1]), "=r"(r[2]), "=r"(r[3]) : "r"(addr));
}

// ---- fp16 NT GEMM (fp32 accum): C[m,n] = sum_k A[m,k]*B[n,k], tile 128x64 ----
// EPI: 0 none | 1 +x0[n] | 2 softplus(+x0[n]) | 3 x1h[m,n]*sigmoid((+x0[n])*x2p[n])
//      | 4 paired swiglu: out[m, n/2] = silu(even)*odd | 5 moe scatter (+x0[e*D+n])
//      | 6 v*x0[bz*L+m] | 7 v + (bz==2 ? x0[n] : 0)
template<int EPI, bool GATHER, bool OUTH>
__global__ void __launch_bounds__(256)
gemm_h(const __half* __restrict__ A, const __half* __restrict__ B, void* __restrict__ Cp_,
       int M, int N, int K, int lda, int ldb, int ldc,
       long long sA, long long sB, long long sC,
       const float* __restrict__ x0, const __half* __restrict__ x1h,
       const float* __restrict__ x2p, int eidx)
{
    constexpr int BM = 128, BN = 64;
    constexpr int MT = 2, NT = 4;
    constexpr int CPR = BK/8;
    constexpr int CA = BM*CPR/256;
    constexpr int CB = BN*CPR/256;
    extern __shared__ __half smem[];
    __half* Asm = smem;
    __half* Bsm = smem + NSTG*BM*LDSH;

    int bm = blockIdx.y, bn = blockIdx.x, bz = blockIdx.z;
    int e = eidx;
    if (eidx == -2) e = bz;
    if (e >= 0) M = g_cnt[e];
    int row0 = bm*BM, col0 = bn*BN;
    if (row0 >= M) return;
    A += bz*sA; B += bz*sB;

    int tid = threadIdx.x;
    int lane = tid & 31, warp = tid >> 5;
    int wm = warp >> 1, wn = warp & 1;
    int g  = lane >> 2, t4 = lane & 3;

    const __half* aptr[CA]; int adst[CA]; bool avp[CA];
    #pragma unroll
    for (int i = 0; i < CA; i++){
        int ci = tid + i*256;
        int r = ci / CPR, s = ci % CPR;
        int gm = row0 + r;
        bool v = gm < M;
        long long src = 0;
        if (v) src = GATHER ? (long long)g_tok[e*L + gm] : gm;
        aptr[i] = A + src*lda + s*8;
        adst[i] = r*LDSH + s*8;
        avp[i]  = v;
    }
    const __half* bptr[CB]; int bdst[CB]; bool bvp[CB];
    #pragma unroll
    for (int i = 0; i < CB; i++){
        int ci = tid + i*256;
        int r = ci / CPR, s = ci % CPR;
        int gn = col0 + r;
        bool v = gn < N;
        bptr[i] = B + (long long)(v ? gn : 0)*ldb + s*8;
        bdst[i] = r*LDSH + s*8;
        bvp[i]  = v;
    }

    unsigned asmem0 = (unsigned)__cvta_generic_to_shared(Asm);
    unsigned bsmem0 = (unsigned)__cvta_generic_to_shared(Bsm);
    unsigned aoff[MT], boff[NT/2];
    #pragma unroll
    for (int mt = 0; mt < MT; mt++)
        aoff[mt] = (unsigned)(((wm*32 + mt*16 + (lane & 15))*LDSH + ((lane >> 4) << 3)) * 2);
    #pragma unroll
    for (int j = 0; j < NT/2; j++)
        boff[j] = (unsigned)(((wn*32 + j*16 + (lane & 7) + ((lane & 16) ? 8 : 0))*LDSH
                              + ((lane & 8) ? 8 : 0)) * 2);

    int NTILES = K / BK;
    #pragma unroll
    for (int s = 0; s < NSTG-1; s++){
        if (s < NTILES){
            #pragma unroll
            for (int i = 0; i < CA; i++) cp16(&Asm[s*BM*LDSH + adst[i]], aptr[i] + s*BK, avp[i]);
            #pragma unroll
            for (int i = 0; i < CB; i++) cp16(&Bsm[s*BN*LDSH + bdst[i]], bptr[i] + s*BK, bvp[i]);
        }
        cpcommit();
    }
    cpwait<NSTG-2>();
    __syncthreads();

    float acc[MT][NT][4];
    #pragma unroll
    for (int i = 0; i < MT; i++)
        #pragma unroll
        for (int j = 0; j < NT; j++)
            #pragma unroll
            for (int c = 0; c < 4; c++) acc[i][j][c] = 0.f;

    for (int kt = 0; kt < NTILES; kt++){
        int nxt = kt + NSTG - 1;
        if (nxt < NTILES){
            int s = nxt % NSTG;
            #pragma unroll
            for (int i = 0; i < CA; i++) cp16(&Asm[s*BM*LDSH + adst[i]], aptr[i] + nxt*BK, avp[i]);
            #pragma unroll
            for (int i = 0; i < CB; i++) cp16(&Bsm[s*BN*LDSH + bdst[i]], bptr[i] + nxt*BK, bvp[i]);
        }
        cpcommit();

        unsigned aBase = asmem0 + (unsigned)((kt % NSTG)*BM*LDSH*2);
        unsigned bBase = bsmem0 + (unsigned)((kt % NSTG)*BN*LDSH*2);
        #pragma unroll
        for (int kp = 0; kp < BK/16; kp++){
            unsigned kb2 = kp*16*2;
            unsigned a[MT][4], bb[NT/2][4];
            #pragma unroll
            for (int mt = 0; mt < MT; mt++) ldsm4(a[mt], aBase + kb2 + aoff[mt]);
            #pragma unroll
            for (int j = 0; j < NT/2; j++) ldsm4(bb[j], bBase + kb2 + boff[j]);
            #pragma unroll
            for (int mt = 0; mt < MT; mt++)
                #pragma unroll
                for (int nt = 0; nt < NT; nt++)
                    mma16(acc[mt][nt], a[mt], &bb[nt >> 1][(nt & 1)*2]);
        }
        cpwait<NSTG-2>();
        __syncthreads();
    }

    float* Cf = (float*)Cp_; __half* Ch = (__half*)Cp_;
    if (OUTH) Ch += bz*sC; else Cf += bz*sC;
    int mbase = row0 + wm*32, nbase = col0 + wn*32;
    #pragma unroll
    for (int mt = 0; mt < MT; mt++){
        #pragma unroll
        for (int nt = 0; nt < NT; nt++){
            if (EPI == 4){
                #pragma unroll
                for (int c = 0; c < 4; c += 2){
                    int m = mbase + mt*16 + g + (c >= 2 ? 8 : 0);
                    int n = nbase + nt*8 + t4*2;
                    if (m >= M) continue;
                    float a = acc[mt][nt][c];
                    float gg = acc[mt][nt][c+1];
                    float r = a/(1.f + __expf(-a))*gg;
                    Ch[(long long)m*ldc + (n >> 1)] = __float2half_rn(r);
                }
                continue;
            }
            #pragma unroll
            for (int c = 0; c < 4; c++){
                int m = mbase + mt*16 + g + (c >= 2 ? 8 : 0);
                int n = nbase + nt*8 + t4*2 + (c & 1);
                if (m >= M || n >= N) continue;
                float v = acc[mt][nt][c];
                float r;
                if (EPI == 0){
                    r = v;
                } else if (EPI == 1){
                    r = v + x0[n];
                } else if (EPI == 2){
                    float zz = v + x0[n];
                    r = fmaxf(zz, 0.f) + log1pf(__expf(-fabsf(zz)));
                } else if (EPI == 3){
                    float zz = (v + x0[n]) * x2p[n];
                    r = __half2float(x1h[(long long)m*ldc + n]) / (1.f + __expf(-zz));
                } else if (EPI == 5){
                    int tok = g_tok[e*L + m];
                    int sl  = g_slot[e*L + m];
                    float w = sl ? g_w1[tok] : g_w0[tok];
                    g_moe[((long long)sl*L + tok)*D + n] = w * (v + x0[(long long)e*D + n]);
                    continue;
                } else if (EPI == 6){
                    r = v * x0[(long long)bz*L + m];
                } else { // EPI 7: bias only for z==2 (pw)
                    r = v + (bz == 2 ? x0[n] : 0.f);
                }
                if (OUTH) Ch[(long long)m*ldc + n] = __float2half_rn(r);
                else      Cf[(long long)m*ldc + n] = r;
            }
        }
    }
}

// ------------------ conversion / elementwise kernels ------------------
__global__ void f2h_kernel(const float* __restrict__ s, __half* __restrict__ d, long long n){
    long long i = ((long long)blockIdx.x*256 + threadIdx.x)*4;
    if (i >= n) return;
    float4 v = *(const float4*)(s + i);
    __half2* o = (__half2*)(d + i);
    o[0] = __floats2half2_rn(v.x, v.y);
    o[1] = __floats2half2_rn(v.z, v.w);
}

__global__ void f2h6_kernel(
    const float* s0, __half* d0, long long n0,
    const float* s1, __half* d1, long long n1,
    const float* s2, __half* d2, long long n2,
    const float* s3, __half* d3, long long n3,
    const float* s4, __half* d4, long long n4,
    const float* s5, __half* d5, long long n5)
{
    long long i = ((long long)blockIdx.x*256 + threadIdx.x)*4;
    const float* s; __half* d;
    if (i < n0){ s = s0; d = d0; }
    else if ((i -= n0) < n1){ s = s1; d = d1; }
    else if ((i -= n1) < n2){ s = s2; d = d2; }
    else if ((i -= n2) < n3){ s = s3; d = d3; }
    else if ((i -= n3) < n4){ s = s4; d = d4; }
    else if ((i -= n4) < n5){ s = s5; d = d5; }
    else return;
    float4 v = *(const float4*)(s + i);
    __half2* o = (__half2*)(d + i);
    o[0] = __floats2half2_rn(v.x, v.y);
    o[1] = __floats2half2_rn(v.z, v.w);
}

__global__ void f2h_w1_kernel(const float* __restrict__ s, __half* __restrict__ d){
    long long ri = (long long)blockIdx.x;
    long long e2 = ri / (2*HID);
    long long r  = ri % (2*HID);
    long long srcr = e2*2*HID + ((r & 1) ? (HID + (r >> 1)) : (r >> 1));
    const float4* sp = (const float4*)(s + srcr*D);
    __half2* dp = (__half2*)(d + ri*D);
    for (int c = threadIdx.x; c < D/4; c += 256){
        float4 v = sp[c];
        dp[c*2+0] = __floats2half2_rn(v.x, v.y);
        dp[c*2+1] = __floats2half2_rn(v.z, v.w);
    }
}

__global__ void packqkv_kernel(const float* __restrict__ qw, const float* __restrict__ kw,
                               const float* __restrict__ vw){
    int r = blockIdx.x;
    const float* src = (r < 1024) ? (qw + (long long)r*D)
                     : (r < 1536) ? (kw + (long long)(r-1024)*D)
                                  : (vw + (long long)(r-1536)*D);
    __half2* dp = (__half2*)(g_wqkvH + (long long)r*D);
    const float4* s = (const float4*)src;
    for (int c = threadIdx.x; c < D/4; c += 256){
        float4 v = s[c];
        dp[c*2+0] = __floats2half2_rn(v.x, v.y);
        dp[c*2+1] = __floats2half2_rn(v.z, v.w);
    }
}

__global__ void rms_kernel(const float* __restrict__ in, const float* __restrict__ w,
                           float* __restrict__ outF, __half* __restrict__ outH){
    int t = blockIdx.x;
    const float* row = in + (long long)t*D;
    __shared__ float sred[8];
    __shared__ float sscale;
    float ss = 0.f;
    for (int d = threadIdx.x; d < D; d += 256){ float v = row[d]; ss += v*v; }
    ss = warpSum(ss);
    if ((threadIdx.x & 31) == 0) sred[threadIdx.x >> 5] = ss;
    __syncthreads();
    if (threadIdx.x == 0){
        float s = 0.f;
        #pragma unroll
        for (int i = 0; i < 8; i++) s += sred[i];
        sscale = rsqrtf(s*(1.f/D) + 1e-6f);
    }
    __syncthreads();
    float sc = sscale;
    for (int d = threadIdx.x; d < D; d += 256){
        float v = row[d]*sc*w[d];
        if (outF) outF[(long long)t*D + d] = v;
        if (outH) outH[(long long)t*D + d] = __float2half_rn(v);
    }
}

__global__ void router_kernel(const float* __restrict__ rw){
    int t = blockIdx.x;
    __shared__ float sm[8][4];
    float acc[4] = {0,0,0,0};
    for (int d = threadIdx.x; d < D; d += 256){
        float xv = g_xn[(long long)t*D + d];
        #pragma unroll
        for (int j = 0; j < 4; j++) acc[j] += xv*rw[j*D + d];
    }
    #pragma unroll
    for (int j = 0; j < 4; j++) acc[j] = warpSum(acc[j]);
    if ((threadIdx.x & 31) == 0){
        #pragma unroll
        for (int j = 0; j < 4; j++) sm[threadIdx.x >> 5][j] = acc[j];
    }
    __syncthreads();
    if (threadIdx.x == 0){
        float lg[4];
        #pragma unroll
        for (int j = 0; j < 4; j++){ float s = 0.f; for (int w2 = 0; w2 < 8; w2++) s += sm[w2][j]; lg[j] = s; }
        float mx = fmaxf(fmaxf(lg[0], lg[1]), fmaxf(lg[2], lg[3]));
        float sum = 0.f;
        #pragma unroll
        for (int j = 0; j < 4; j++){ lg[j] = __expf(lg[j] - mx); sum += lg[j]; }
        const float c[4] = {0.5f, 0.2f, 0.15f, 0.15f};
        float s2 = 0.f;
        #pragma unroll
        for (int j = 0; j < 4; j++){ lg[j] = lg[j]/sum*c[j]; s2 += lg[j]; }
        #pragma unroll
        for (int j = 0; j < 4; j++) g_weights[t*4 + j] = lg[j]/s2;
    }
}

__global__ void scan_kernel(const float* __restrict__ A_log, const float* __restrict__ Dp){
    int w = threadIdx.x >> 5, lane = threadIdx.x & 31;
    int d = blockIdx.x*4 + w;
    float4 A0;
    A0.x = -__expf(A_log[d*NS + lane*4 + 0]);
    A0.y = -__expf(A_log[d*NS + lane*4 + 1]);
    A0.z = -__expf(A_log[d*NS + lane*4 + 2]);
    A0.w = -__expf(A_log[d*NS + lane*4 + 3]);
    float Dpd = Dp[d];
    float4 h = make_float4(0.f,0.f,0.f,0.f);
    const __half2* __restrict__ P2 = (const __half2*)g_projH;
    for (int t = 0; t < L; t++){
        float2 b0 = __half22float2(P2[t*160 + 32 + lane*2]);
        float2 b1 = __half22float2(P2[t*160 + 32 + lane*2 + 1]);
        float2 c0 = __half22float2(P2[t*160 + 96 + lane*2]);
        float2 c1 = __half22float2(P2[t*160 + 96 + lane*2 + 1]);
        float ddt = __half2float(g_deltaH[t*D + d]);
        float xx  = __half2float(g_snselH[t*D + d]);
        float dx = ddt*xx;
        h.x = __expf(ddt*A0.x)*h.x + dx*b0.x;
        h.y = __expf(ddt*A0.y)*h.y + dx*b0.y;
        h.z = __expf(ddt*A0.z)*h.z + dx*b1.x;
        h.w = __expf(ddt*A0.w)*h.w + dx*b1.y;
        float acc = h.x*c0.x + h.y*c0.y + h.z*c1.x + h.w*c1.y;
        acc = warpSum(acc);
        if (lane == 0)
            g_pinH[t*D + d] = __float2half_rn(acc + g_xn[t*D + d]*Dpd);
    }
}

__global__ void qrope_kernel(const float* __restrict__ qn_w){
    int t = blockIdx.x;
    int h = threadIdx.x >> 5, l = threadIdx.x & 31;
    float a = __half2float(g_qkvH[(long long)t*QKVN + h*HD + l]);
    float b = __half2float(g_qkvH[(long long)t*QKVN + h*HD + l + 32]);
    float ss = warpSum(a*a + b*b);
    float sc = rsqrtf(ss*(1.f/HD) + 1e-6f) * 0.125f;
    a = a*sc*qn_w[l]; b = b*sc*qn_w[l+32];
    float inv = __expf(-(float)l*(1.f/32.f)*9.210340371976184f);
    float s, c; sincosf((float)t*inv, &s, &c);
    long long base = ((long long)h*L + t)*HD;
    g_qrH[base + l]      = __float2half_rn(a*c - b*s);
    g_qrH[base + l + 32] = __float2half_rn(b*c + a*s);
}

__global__ void kvrope_kernel(const float* __restrict__ kn_w){
    int t = blockIdx.x;
    int w = threadIdx.x >> 5, l = threadIdx.x & 31;
    if (w < 8){
        int j = w;
        float a = __half2float(g_qkvH[(long long)t*QKVN + 1024 + j*HD + l]);
        float b = __half2float(g_qkvH[(long long)t*QKVN + 1024 + j*HD + l + 32]);
        float ss = warpSum(a*a + b*b);
        float sc = rsqrtf(ss*(1.f/HD) + 1e-6f);
        a = a*sc*kn_w[l]; b = b*sc*kn_w[l+32];
        float inv = __expf(-(float)l*(1.f/32.f)*9.210340371976184f);
        float s, c; sincosf((float)t*inv, &s, &c);
        __half o1 = __float2half_rn(a*c - b*s);
        __half o2 = __float2half_rn(b*c + a*s);
        #pragma unroll
        for (int r = 0; r < 2; r++){
            long long base = ((long long)(2*j + r)*L + t)*HD;
            g_krH[base + l]      = o1;
            g_krH[base + l + 32] = o2;
        }
    } else {
        int j = w - 8;
        __half a = g_qkvH[(long long)t*QKVN + 1536 + j*HD + l];
        __half b = g_qkvH[(long long)t*QKVN + 1536 + j*HD + l + 32];
        #pragma unroll
        for (int r = 0; r < 2; r++){
            long long hb = (long long)(2*j + r)*HD;
            g_vtH[(hb + l)*L + t]      = a;
            g_vtH[(hb + l + 32)*L + t] = b;
        }
    }
}

__global__ void softmax_kernel(){
    __half* row = g_scoresH + (long long)blockIdx.x*L;
    __shared__ float sred[8];
    int tid = threadIdx.x;
    float mx = -1e30f;
    for (int i = tid; i < L; i += 256) mx = fmaxf(mx, __half2float(row[i]));
    #pragma unroll
    for (int o = 16; o; o >>= 1) mx = fmaxf(mx, __shfl_xor_sync(0xffffffffu, mx, o));
    if ((tid & 31) == 0) sred[tid >> 5] = mx;
    __syncthreads();
    if (tid == 0){ float m = sred[0]; for (int i = 1; i < 8; i++) m = fmaxf(m, sred[i]); sred[0] = m; }
    __syncthreads();
    mx = sred[0];
    __syncthreads();
    float s = 0.f;
    for (int i = tid; i < L; i += 256){
        float e = __expf(__half2float(row[i]) - mx);
        row[i] = __float2half_rn(e);
        s += e;
    }
    s = warpSum(s);
    if ((tid & 31) == 0) sred[tid >> 5] = s;
    __syncthreads();
    if (tid == 0){
        float t2 = 0.f;
        for (int i = 0; i < 8; i++) t2 += sred[i];
        g_sinv[blockIdx.x] = 1.f/t2;
    }
}

__global__ void conv_silu_kernel(const float* __restrict__ dww, const float* __restrict__ dwb){
    int t = blockIdx.x;
    for (int d = threadIdx.x; d < D; d += 256){
        float v = g_xn[(long long)t*D + d]*dww[d*3+1] + dwb[d];
        if (t > 0)     v += g_xn[(long long)(t-1)*D + d]*dww[d*3+0];
        if (t < L-1)   v += g_xn[(long long)(t+1)*D + d]*dww[d*3+2];
        g_pinH[2*L*D + (long long)t*D + d] = __float2half_rn(v/(1.f + __expf(-v)));
    }
}

__global__ void mix_kernel(const float* __restrict__ x, const float* __restrict__ mem){
    int t = blockIdx.x;
    float w0 = g_weights[t*4+0], w1 = g_weights[t*4+1];
    float w2 = g_weights[t*4+2], w3 = g_weights[t*4+3];
    for (int d = threadIdx.x; d < D; d += 256){
        long long i = (long long)t*D + d;
        float v = x[i] + w0*g_pout[i] + w1*g_pout[(long long)L*D + i]
                + w2*g_pout[2LL*L*D + i] + w3*mem[i];
        g_x2[i] = v;
        g_x2H[i] = __float2half_rn(v);
    }
}

__global__ void gate_kernel(const float* __restrict__ n2w, const float* __restrict__ gw){
    int t = blockIdx.x;
    __shared__ float sred[8];
    __shared__ float sacc[8][8];
    __shared__ float sscale;
    const float* row = g_x2 + (long long)t*D;
    float ss = 0.f;
    for (int d = threadIdx.x; d < D; d += 256){ float v = row[d]; ss += v*v; }
    ss = warpSum(ss);
    if ((threadIdx.x & 31) == 0) sred[threadIdx.x >> 5] = ss;
    __syncthreads();
    if (threadIdx.x == 0){
        float s = 0.f; for (int i = 0; i < 8; i++) s += sred[i];
        sscale = rsqrtf(s*(1.f/D) + 1e-6f);
    }
    __syncthreads();
    float sc = sscale;
    float acc[8] = {0,0,0,0,0,0,0,0};
    for (int d = threadIdx.x; d < D; d += 256){
        float xv = row[d]*sc*n2w[d];
        #pragma unroll
        for (int e = 0; e < 8; e++) acc[e] += xv*gw[e*D + d];
    }
    #pragma unroll
    for (int e = 0; e < 8; e++) acc[e] = warpSum(acc[e]);
    if ((threadIdx.x & 31) == 0){
        #pragma unroll
        for (int e = 0; e < 8; e++) sacc[threadIdx.x >> 5][e] = acc[e];
    }
    __syncthreads();
    if (threadIdx.x == 0){
        float lg[8];
        #pragma unroll
        for (int e = 0; e < 8; e++){ float s = 0.f; for (int w2 = 0; w2 < 8; w2++) s += sacc[w2][e]; lg[e] = s; }
        float v1 = -1e30f; int i1 = 0;
        for (int e = 0; e < 8; e++) if (lg[e] > v1){ v1 = lg[e]; i1 = e; }
        float v2 = -1e30f; int i2 = 0;
        for (int e = 0; e < 8; e++) if (e != i1 && lg[e] > v2){ v2 = lg[e]; i2 = e; }
        g_vals[t*2+0] = v1; g_vals[t*2+1] = v2;
        g_topidx[t*2+0] = i1; g_topidx[t*2+1] = i2;
    }
}

__global__ void colsoftmax_kernel(){
    int i = blockIdx.x;
    int t = threadIdx.x;
    __shared__ float red[32];
    float v = g_vals[t*2 + i];
    float m = v;
    #pragma unroll
    for (int o = 16; o; o >>= 1) m = fmaxf(m, __shfl_xor_sync(0xffffffffu, m, o));
    if ((t & 31) == 0) red[t >> 5] = m;
    __syncthreads();
    if (t == 0){ float mm = red[0]; for (int k = 1; k < 32; k++) mm = fmaxf(mm, red[k]); red[0] = mm; }
    __syncthreads();
    m = red[0];
    __syncthreads();
    float e = __expf(v - m);
    float s = e;
    #pragma unroll
    for (int o = 16; o; o >>= 1) s += __shfl_xor_sync(0xffffffffu, s, o);
    if ((t & 31) == 0) red[t >> 5] = s;
    __syncthreads();
    if (t == 0){ float sm = 0.f; for (int k = 0; k < 32; k++) sm += red[k]; red[0] = sm; }
    __syncthreads();
    float w = e / red[0];
    if (i == 0) g_w0[t] = w; else g_w1[t] = w;
}

__global__ void zero_cnt_kernel(){
    if (threadIdx.x < E) g_cnt[threadIdx.x] = 0;
}

__global__ void compact_kernel(){
    int t = blockIdx.x*256 + threadIdx.x;
    if (t >= L) return;
    #pragma unroll
    for (int i = 0; i < 2; i++){
        int e = g_topidx[t*2 + i];
        int p = atomicAdd(&g_cnt[e], 1);
        g_tok[e*L + p] = t;
        g_slot[e*L + p] = i;
    }
}

__global__ void final_kernel(float* __restrict__ out){
    int t = blockIdx.x;
    for (int d = threadIdx.x; d < D; d += 256){
        long long i = (long long)t*D + d;
        out[i] = g_x2[i] + 0.1f*(g_moe[i] + g_moe[(long long)L*D + i]);
    }
}

// ------------------ launch ------------------
namespace {
constexpr int SMEMH = NSTG*(128+64)*LDSH*2;  // 82944 bytes
inline dim3 grd(int M, int N, int Z){ return dim3(N/64, (M+127)/128, Z); }
inline int cgrid(long long n){ return (int)((n/4 + 255)/256); }
}

extern "C" void kernel_launch(void* const* d_in, const int* in_sizes, int n_in,
                              void* d_out, int out_size)
{
    const float* x         = (const float*)d_in[0];
    const float* mem       = (const float*)d_in[1];
    const float* norm1_w   = (const float*)d_in[2];
    const float* router_w  = (const float*)d_in[3];
    const float* ssm_norm_w= (const float*)d_in[4];
    const float* x_proj_w  = (const float*)d_in[5];
    const float* dt_proj_w = (const float*)d_in[6];
    const float* dt_proj_b = (const float*)d_in[7];
    const float* A_log     = (const float*)d_in[8];
    const float* D_param   = (const float*)d_in[9];
    const float* ssm_out_w = (const float*)d_in[10];
    const float* sel_w     = (const float*)d_in[11];
    const float* sel_b     = (const float*)d_in[12];
    const float* sel_gate  = (const float*)d_in[13];
    const float* q_w       = (const float*)d_in[14];
    const float* k_w       = (const float*)d_in[15];
    const float* v_w       = (const float*)d_in[16];
    const float* o_w       = (const float*)d_in[17];
    const float* qn_w      = (const float*)d_in[18];
    const float* kn_w      = (const float*)d_in[19];
    const float* dw_w      = (const float*)d_in[20];
    const float* dw_b      = (const float*)d_in[21];
    const float* pw_w      = (const float*)d_in[22];
    const float* pw_b      = (const float*)d_in[23];
    const float* norm2_w   = (const float*)d_in[24];
    const float* gate_w    = (const float*)d_in[25];
    const float* e_w1      = (const float*)d_in[26];
    const float* e_w2      = (const float*)d_in[27];
    const float* e_lw      = (const float*)d_in[28];
    const float* e_lb      = (const float*)d_in[29];
    float* out = (float*)d_out;

    float *p_xn, *p_pout, *p_sinv, *p_x2;
    __half *p_xnH, *p_snH, *p_snselH, *p_projH, *p_deltaH, *p_pinH;
    __half *p_wqkvH, *p_qkvH, *p_qrH, *p_krH, *p_vtH, *p_scoresH;
    __half *p_x2H, *p_hhH, *p_yH;
    __half *p_selwH, *p_xpwH, *p_dtwH, *p_wprojH, *p_ew1H, *p_ew2H, *p_elwH;
    cudaGetSymbolAddress((void**)&p_xn, g_xn);
    cudaGetSymbolAddress((void**)&p_xnH, g_xnH);
    cudaGetSymbolAddress((void**)&p_snH, g_snH);
    cudaGetSymbolAddress((void**)&p_snselH, g_snselH);
    cudaGetSymbolAddress((void**)&p_projH, g_projH);
    cudaGetSymbolAddress((void**)&p_deltaH, g_deltaH);
    cudaGetSymbolAddress((void**)&p_pinH, g_pinH);
    cudaGetSymbolAddress((void**)&p_pout, g_pout);
    cudaGetSymbolAddress((void**)&p_wqkvH, g_wqkvH);
    cudaGetSymbolAddress((void**)&p_qkvH, g_qkvH);
    cudaGetSymbolAddress((void**)&p_qrH, g_qrH);
    cudaGetSymbolAddress((void**)&p_krH, g_krH);
    cudaGetSymbolAddress((void**)&p_vtH, g_vtH);
    cudaGetSymbolAddress((void**)&p_scoresH, g_scoresH);
    cudaGetSymbolAddress((void**)&p_sinv, g_sinv);
    cudaGetSymbolAddress((void**)&p_x2, g_x2);
    cudaGetSymbolAddress((void**)&p_x2H, g_x2H);
    cudaGetSymbolAddress((void**)&p_hhH, g_hhH);
    cudaGetSymbolAddress((void**)&p_yH, g_yH);
    cudaGetSymbolAddress((void**)&p_selwH, g_selwH);
    cudaGetSymbolAddress((void**)&p_xpwH, g_xpwH);
    cudaGetSymbolAddress((void**)&p_dtwH, g_dtwH);
    cudaGetSymbolAddress((void**)&p_wprojH, g_wprojH);
    cudaGetSymbolAddress((void**)&p_ew1H, g_ew1H);
    cudaGetSymbolAddress((void**)&p_ew2H, g_ew2H);
    cudaGetSymbolAddress((void**)&p_elwH, g_elwH);

    #define SETSM(KER) cudaFuncSetAttribute((const void*)&KER, cudaFuncAttributeMaxDynamicSharedMemorySize, SMEMH)
    SETSM((gemm_h<3,false,true>));
    SETSM((gemm_h<0,false,true>));
    SETSM((gemm_h<2,false,true>));
    SETSM((gemm_h<7,false,false>));
    SETSM((gemm_h<6,false,true>));
    SETSM((gemm_h<4,true,true>));
    SETSM((gemm_h<5,false,false>));
    #undef SETSM

    // 0. weight conversions: merged small set + big expert sets
    {
        long long n0 = (long long)D*D, n1 = (long long)PRJ*D, n2 = (long long)D*DT;
        long long tot = n0*4 + n1 + n2;
        f2h6_kernel<<<cgrid(tot), 256>>>(
            sel_w, p_selwH, n0,
            x_proj_w, p_xpwH, n1,
            dt_proj_w, p_dtwH, n2,
            ssm_out_w, p_wprojH, n0,
            o_w, p_wprojH + (long long)D*D, n0,
            pw_w, p_wprojH + 2LL*D*D, n0);
    }
    f2h_w1_kernel<<<E*2*HID, 256>>>(e_w1, p_ew1H);
    f2h_kernel<<<cgrid((long long)E*D*HID), 256>>>(e_w2, p_ew2H, (long long)E*D*HID);
    f2h_kernel<<<cgrid((long long)E*D*D), 256>>>(e_lw, p_elwH, (long long)E*D*D);
    packqkv_kernel<<<QKVN, 256>>>(q_w, k_w, v_w);

    // 1. xn = rms(x); router; conv (slice2) early
    rms_kernel<<<L, 256>>>(x, norm1_w, p_xn, p_xnH);
    router_kernel<<<L, 256>>>(router_w);
    conv_silu_kernel<<<L, 256>>>(dw_w, dw_b);
    // 2. sn = rms(xn)
    rms_kernel<<<L, 256>>>(p_xn, ssm_norm_w, nullptr, p_snH);
    // 3. sn_sel
    gemm_h<3,false,true><<<grd(L, D, 1), 256, SMEMH>>>(p_snH, p_selwH, p_snselH,
        L, D, D, D, D, D, 0, 0, 0, sel_b, p_snH, sel_gate, -1);
    // 4. proj
    gemm_h<0,false,true><<<grd(L, PRJ, 1), 256, SMEMH>>>(p_snselH, p_xpwH, p_projH,
        L, PRJ, D, D, D, PRJ, 0, 0, 0, nullptr, nullptr, nullptr, -1);
    // 5. delta
    gemm_h<2,false,true><<<grd(L, D, 1), 256, SMEMH>>>(p_projH, p_dtwH, p_deltaH,
        L, D, DT, PRJ, DT, D, 0, 0, 0, dt_proj_b, nullptr, nullptr, -1);
    // 6. scan (writes slice0 of pinH)
    scan_kernel<<<D/4, 128>>>(A_log, D_param);
    // 7. fused qkv
    gemm_h<0,false,true><<<grd(L, QKVN, 1), 256, SMEMH>>>(p_xnH, p_wqkvH, p_qkvH,
        L, QKVN, D, D, D, QKVN, 0, 0, 0, nullptr, nullptr, nullptr, -1);
    // 8. rope
    qrope_kernel<<<L, 512>>>(qn_w);
    kvrope_kernel<<<L, 512>>>(kn_w);
    // 9. scores
    gemm_h<0,false,true><<<grd(L, L, H), 256, SMEMH>>>(p_qrH, p_krH, p_scoresH,
        L, L, HD, HD, HD, L,
        (long long)L*HD, (long long)L*HD, (long long)L*L, nullptr, nullptr, nullptr, -1);
    // 10. softmax
    softmax_kernel<<<H*L, 256>>>();
    // 11. attn@v -> slice1 of pinH
    gemm_h<6,false,true><<<grd(L, HD, H), 256, SMEMH>>>(p_scoresH, p_vtH, p_pinH + (long long)L*D,
        L, HD, L, L, L, D,
        (long long)L*L, (long long)HD*L, (long long)HD, p_sinv, nullptr, nullptr, -1);
    // 12. batched output projections (ssm_out | o_w | pw), z=3
    gemm_h<7,false,false><<<grd(L, D, 3), 256, SMEMH>>>(p_pinH, p_wprojH, p_pout,
        L, D, D, D, D, D,
        (long long)L*D, (long long)D*D, (long long)L*D, pw_b, nullptr, nullptr, -1);
    // 13. mix
    mix_kernel<<<L, 256>>>(x, mem);
    // 14. gate + top2 + seq softmax + compaction
    gate_kernel<<<L, 256>>>(norm2_w, gate_w);
    colsoftmax_kernel<<<2, 1024>>>();
    zero_cnt_kernel<<<1, 32>>>();
    compact_kernel<<<(L+255)/256, 256>>>();
    // 15. routed experts — w1 with fused SwiGLU epilogue
    gemm_h<4,true,true><<<grd(L, 2*HID, E), 256, SMEMH>>>(p_x2H, p_ew1H, p_hhH,
        L, 2*HID, D, D, D, HID,
        0, (long long)2*HID*D, (long long)L*HID, nullptr, nullptr, nullptr, -2);
    gemm_h<0,false,true><<<grd(L, D, E), 256, SMEMH>>>(p_hhH, p_ew2H, p_yH,
        L, D, HID, HID, HID, D,
        (long long)L*HID, (long long)D*HID, (long long)L*D, nullptr, nullptr, nullptr, -2);
    gemm_h<5,false,false><<<grd(L, D, E), 256, SMEMH>>>(p_yH, p_elwH, nullptr,
        L, D, D, D, D, D,
        (long long)L*D, (long long)D*D, 0, e_lb, nullptr, nullptr, -2);
    // 16. final
    final_kernel<<<L, 256>>>(out);
}

// round 16
// speedup vs baseline: 1.0056x; 1.0056x over previous
#include <cuda_runtime.h>
#include <cuda_fp16.h>
#include <math.h>

namespace {
constexpr int L   = 1024;
constexpr int D   = 1024;
constexpr int H   = 16;
constexpr int KVH = 8;
constexpr int HD  = 64;
constexpr int NS  = 128;
constexpr int DT  = 64;
constexpr int E   = 8;
constexpr int HID = 4096;
constexpr int PRJ = DT + 2*NS; // 320
constexpr int QKVN = 2048;
constexpr int BK  = 64;
constexpr int NSTG = 3;
constexpr int LDSH = BK + 8;   // 72 halves = 144B rows (conflict-free ldmatrix)
}

// ------------------ scratch: device globals ------------------
__device__ float  g_xn[L*D];
__device__ __half g_xnH[L*D];
__device__ __half g_snH[L*D];
__device__ __half g_snselH[L*D];
__device__ __half g_projH[L*PRJ];
__device__ __half g_deltaH[L*D];
__device__ __half g_pinH[3*L*D];   // slice0: ssm scan out, slice1: attn out, slice2: conv-silu
__device__ float  g_pout[3*L*D];   // batched projection outputs
__device__ __half g_wqkvH[QKVN*D];
__device__ __half g_qkvH[L*QKVN];
__device__ __half g_qrH[H*L*HD];
__device__ __half g_krH[H*L*HD];
__device__ __half g_vtH[H*HD*L];
__device__ __half g_scoresH[H*L*L];
__device__ float  g_sinv[H*L];
__device__ float  g_weights[L*4];
__device__ float  g_x2[L*D];
__device__ __half g_x2H[L*D];
__device__ float  g_vals[L*2];
__device__ int    g_topidx[L*2];
__device__ float  g_w0[L];
__device__ float  g_w1[L];
__device__ int    g_cnt[E];
__device__ int    g_tok[E*L];
__device__ int    g_slot[E*L];
__device__ __half g_hhH[(long long)E*L*HID];
__device__ __half g_yH [(long long)E*L*D];
__device__ float  g_moe[2*L*D];
// half weight shadows
__device__ __half g_selwH[D*D];
__device__ __half g_xpwH[PRJ*D];
__device__ __half g_dtwH[D*DT];
__device__ __half g_wprojH[3*D*D];  // slice0: ssm_out_w, slice1: o_w, slice2: pw_w
__device__ __half g_ew1H[(long long)E*2*HID*D];   // rows interleaved: 2j=a_j, 2j+1=g_j
__device__ __half g_ew2H[(long long)E*D*HID];
__device__ __half g_elwH[(long long)E*D*D];

__device__ __forceinline__ float warpSum(float v){
    #pragma unroll
    for (int o = 16; o; o >>= 1) v += __shfl_xor_sync(0xffffffffu, v, o);
    return v;
}

__device__ __forceinline__ void cp16(__half* smem, const __half* g, bool pred){
    unsigned s = (unsigned)__cvta_generic_to_shared(smem);
    int sz = pred ? 16 : 0;
    asm volatile("cp.async.cg.shared.global [%0], [%1], 16, %2;\n"
                 :: "r"(s), "l"(g), "r"(sz));
}
__device__ __forceinline__ void cpcommit(){ asm volatile("cp.async.commit_group;\n"); }
template<int N> __device__ __forceinline__ void cpwait(){ asm volatile("cp.async.wait_group %0;\n" :: "n"(N)); }

__device__ __forceinline__ void mma16(float* d, const unsigned* a, const unsigned* b){
    asm volatile(
      "mma.sync.aligned.m16n8k16.row.col.f32.f16.f16.f32 "
      "{%0,%1,%2,%3},{%4,%5,%6,%7},{%8,%9},{%0,%1,%2,%3};"
      : "+f"(d[0]), "+f"(d[1]), "+f"(d[2]), "+f"(d[3])
      : "r"(a[0]), "r"(a[1]), "r"(a[2]), "r"(a[3]), "r"(b[0]), "r"(b[1]));
}
__device__ __forceinline__ void ldsm4(unsigned* r, unsigned addr){
    asm volatile("ldmatrix.sync.aligned.m8n8.x4.shared.b16 {%0,%1,%2,%3}, [%4];"
                 : "=r"(r[0]), "=r"(r[1]), "=r"(r[2]), "=r"(r[3]) : "r"(addr));
}

// ---- fp16 NT GEMM (fp32 accum): C[m,n] = sum_k A[m,k]*B[n,k], tile 128x64 ----
// EPI: 0 none | 1 +x0[n] | 2 softplus(+x0[n]) | 3 x1h[m,n]*sigmoid((+x0[n])*x2p[n])
//      | 4 paired swiglu: out[m, n/2] = silu(even)*odd | 5 moe scatter (+x0[e*D+n])
//      | 6 v*x0[bz*L+m] | 7 v + (bz==2 ? x0[n] : 0)
template<int EPI, bool GATHER, bool OUTH>
__global__ void __launch_bounds__(256, 2)
gemm_h(const __half* __restrict__ A, const __half* __restrict__ B, void* __restrict__ Cp_,
       int M, int N, int K, int lda, int ldb, int ldc,
       long long sA, long long sB, long long sC,
       const float* __restrict__ x0, const __half* __restrict__ x1h,
       const float* __restrict__ x2p, int eidx)
{
    constexpr int BM = 128, BN = 64;
    constexpr int MT = 2, NT = 4;
    constexpr int CPR = BK/8;
    constexpr int CA = BM*CPR/256;
    constexpr int CB = BN*CPR/256;
    extern __shared__ __half smem[];
    __half* Asm = smem;
    __half* Bsm = smem + NSTG*BM*LDSH;

    int bm = blockIdx.y, bn = blockIdx.x, bz = blockIdx.z;
    int e = eidx;
    if (eidx == -2) e = bz;
    if (e >= 0) M = g_cnt[e];
    int row0 = bm*BM, col0 = bn*BN;
    if (row0 >= M) return;
    A += bz*sA; B += bz*sB;

    int tid = threadIdx.x;
    int lane = tid & 31, warp = tid >> 5;
    int wm = warp >> 1, wn = warp & 1;
    int g  = lane >> 2, t4 = lane & 3;

    const __half* aptr[CA]; int adst[CA]; bool avp[CA];
    #pragma unroll
    for (int i = 0; i < CA; i++){
        int ci = tid + i*256;
        int r = ci / CPR, s = ci % CPR;
        int gm = row0 + r;
        bool v = gm < M;
        long long src = 0;
        if (v) src = GATHER ? (long long)g_tok[e*L + gm] : gm;
        aptr[i] = A + src*lda + s*8;
        adst[i] = r*LDSH + s*8;
        avp[i]  = v;
    }
    const __half* bptr[CB]; int bdst[CB]; bool bvp[CB];
    #pragma unroll
    for (int i = 0; i < CB; i++){
        int ci = tid + i*256;
        int r = ci / CPR, s = ci % CPR;
        int gn = col0 + r;
        bool v = gn < N;
        bptr[i] = B + (long long)(v ? gn : 0)*ldb + s*8;
        bdst[i] = r*LDSH + s*8;
        bvp[i]  = v;
    }

    unsigned asmem0 = (unsigned)__cvta_generic_to_shared(Asm);
    unsigned bsmem0 = (unsigned)__cvta_generic_to_shared(Bsm);
    unsigned aoff[MT], boff[NT/2];
    #pragma unroll
    for (int mt = 0; mt < MT; mt++)
        aoff[mt] = (unsigned)(((wm*32 + mt*16 + (lane & 15))*LDSH + ((lane >> 4) << 3)) * 2);
    #pragma unroll
    for (int j = 0; j < NT/2; j++)
        boff[j] = (unsigned)(((wn*32 + j*16 + (lane & 7) + ((lane & 16) ? 8 : 0))*LDSH
                              + ((lane & 8) ? 8 : 0)) * 2);

    int NTILES = K / BK;
    #pragma unroll
    for (int s = 0; s < NSTG-1; s++){
        if (s < NTILES){
            #pragma unroll
            for (int i = 0; i < CA; i++) cp16(&Asm[s*BM*LDSH + adst[i]], aptr[i] + s*BK, avp[i]);
            #pragma unroll
            for (int i = 0; i < CB; i++) cp16(&Bsm[s*BN*LDSH + bdst[i]], bptr[i] + s*BK, bvp[i]);
        }
        cpcommit();
    }
    cpwait<NSTG-2>();
    __syncthreads();

    float acc[MT][NT][4];
    #pragma unroll
    for (int i = 0; i < MT; i++)
        #pragma unroll
        for (int j = 0; j < NT; j++)
            #pragma unroll
            for (int c = 0; c < 4; c++) acc[i][j][c] = 0.f;

    for (int kt = 0; kt < NTILES; kt++){
        int nxt = kt + NSTG - 1;
        if (nxt < NTILES){
            int s = nxt % NSTG;
            #pragma unroll
            for (int i = 0; i < CA; i++) cp16(&Asm[s*BM*LDSH + adst[i]], aptr[i] + nxt*BK, avp[i]);
            #pragma unroll
            for (int i = 0; i < CB; i++) cp16(&Bsm[s*BN*LDSH + bdst[i]], bptr[i] + nxt*BK, bvp[i]);
        }
        cpcommit();

        unsigned aBase = asmem0 + (unsigned)((kt % NSTG)*BM*LDSH*2);
        unsigned bBase = bsmem0 + (unsigned)((kt % NSTG)*BN*LDSH*2);
        #pragma unroll
        for (int kp = 0; kp < BK/16; kp++){
            unsigned kb2 = kp*16*2;
            unsigned a[MT][4], bb[NT/2][4];
            #pragma unroll
            for (int mt = 0; mt < MT; mt++) ldsm4(a[mt], aBase + kb2 + aoff[mt]);
            #pragma unroll
            for (int j = 0; j < NT/2; j++) ldsm4(bb[j], bBase + kb2 + boff[j]);
            #pragma unroll
            for (int mt = 0; mt < MT; mt++)
                #pragma unroll
                for (int nt = 0; nt < NT; nt++)
                    mma16(acc[mt][nt], a[mt], &bb[nt >> 1][(nt & 1)*2]);
        }
        cpwait<NSTG-2>();
        __syncthreads();
    }

    float* Cf = (float*)Cp_; __half* Ch = (__half*)Cp_;
    if (OUTH) Ch += bz*sC; else Cf += bz*sC;
    int mbase = row0 + wm*32, nbase = col0 + wn*32;
    #pragma unroll
    for (int mt = 0; mt < MT; mt++){
        #pragma unroll
        for (int nt = 0; nt < NT; nt++){
            if (EPI == 4){
                #pragma unroll
                for (int c = 0; c < 4; c += 2){
                    int m = mbase + mt*16 + g + (c >= 2 ? 8 : 0);
                    int n = nbase + nt*8 + t4*2;
                    if (m >= M) continue;
                    float a = acc[mt][nt][c];
                    float gg = acc[mt][nt][c+1];
                    float r = a/(1.f + __expf(-a))*gg;
                    Ch[(long long)m*ldc + (n >> 1)] = __float2half_rn(r);
                }
                continue;
            }
            #pragma unroll
            for (int c = 0; c < 4; c++){
                int m = mbase + mt*16 + g + (c >= 2 ? 8 : 0);
                int n = nbase + nt*8 + t4*2 + (c & 1);
                if (m >= M || n >= N) continue;
                float v = acc[mt][nt][c];
                float r;
                if (EPI == 0){
                    r = v;
                } else if (EPI == 1){
                    r = v + x0[n];
                } else if (EPI == 2){
                    float zz = v + x0[n];
                    r = fmaxf(zz, 0.f) + log1pf(__expf(-fabsf(zz)));
                } else if (EPI == 3){
                    float zz = (v + x0[n]) * x2p[n];
                    r = __half2float(x1h[(long long)m*ldc + n]) / (1.f + __expf(-zz));
                } else if (EPI == 5){
                    int tok = g_tok[e*L + m];
                    int sl  = g_slot[e*L + m];
                    float w = sl ? g_w1[tok] : g_w0[tok];
                    g_moe[((long long)sl*L + tok)*D + n] = w * (v + x0[(long long)e*D + n]);
                    continue;
                } else if (EPI == 6){
                    r = v * x0[(long long)bz*L + m];
                } else { // EPI 7
                    r = v + (bz == 2 ? x0[n] : 0.f);
                }
                if (OUTH) Ch[(long long)m*ldc + n] = __float2half_rn(r);
                else      Cf[(long long)m*ldc + n] = r;
            }
        }
    }
}

// ------------------ conversion / elementwise kernels ------------------
__global__ void f2h_kernel(const float* __restrict__ s, __half* __restrict__ d, long long n){
    long long i = ((long long)blockIdx.x*256 + threadIdx.x)*4;
    if (i >= n) return;
    float4 v = *(const float4*)(s + i);
    __half2* o = (__half2*)(d + i);
    o[0] = __floats2half2_rn(v.x, v.y);
    o[1] = __floats2half2_rn(v.z, v.w);
}

__global__ void f2h6_kernel(
    const float* s0, __half* d0, long long n0,
    const float* s1, __half* d1, long long n1,
    const float* s2, __half* d2, long long n2,
    const float* s3, __half* d3, long long n3,
    const float* s4, __half* d4, long long n4,
    const float* s5, __half* d5, long long n5)
{
    long long i = ((long long)blockIdx.x*256 + threadIdx.x)*4;
    const float* s; __half* d;
    if (i < n0){ s = s0; d = d0; }
    else if ((i -= n0) < n1){ s = s1; d = d1; }
    else if ((i -= n1) < n2){ s = s2; d = d2; }
    else if ((i -= n2) < n3){ s = s3; d = d3; }
    else if ((i -= n3) < n4){ s = s4; d = d4; }
    else if ((i -= n4) < n5){ s = s5; d = d5; }
    else return;
    float4 v = *(const float4*)(s + i);
    __half2* o = (__half2*)(d + i);
    o[0] = __floats2half2_rn(v.x, v.y);
    o[1] = __floats2half2_rn(v.z, v.w);
}

__global__ void f2h_w1_kernel(const float* __restrict__ s, __half* __restrict__ d){
    long long ri = (long long)blockIdx.x;
    long long e2 = ri / (2*HID);
    long long r  = ri % (2*HID);
    long long srcr = e2*2*HID + ((r & 1) ? (HID + (r >> 1)) : (r >> 1));
    const float4* sp = (const float4*)(s + srcr*D);
    __half2* dp = (__half2*)(d + ri*D);
    for (int c = threadIdx.x; c < D/4; c += 256){
        float4 v = sp[c];
        dp[c*2+0] = __floats2half2_rn(v.x, v.y);
        dp[c*2+1] = __floats2half2_rn(v.z, v.w);
    }
}

__global__ void packqkv_kernel(const float* __restrict__ qw, const float* __restrict__ kw,
                               const float* __restrict__ vw){
    int r = blockIdx.x;
    const float* src = (r < 1024) ? (qw + (long long)r*D)
                     : (r < 1536) ? (kw + (long long)(r-1024)*D)
                                  : (vw + (long long)(r-1536)*D);
    __half2* dp = (__half2*)(g_wqkvH + (long long)r*D);
    const float4* s = (const float4*)src;
    for (int c = threadIdx.x; c < D/4; c += 256){
        float4 v = s[c];
        dp[c*2+0] = __floats2half2_rn(v.x, v.y);
        dp[c*2+1] = __floats2half2_rn(v.z, v.w);
    }
}

__global__ void rms_kernel(const float* __restrict__ in, const float* __restrict__ w,
                           float* __restrict__ outF, __half* __restrict__ outH){
    int t = blockIdx.x;
    const float* row = in + (long long)t*D;
    __shared__ float sred[8];
    __shared__ float sscale;
    float ss = 0.f;
    for (int d = threadIdx.x; d < D; d += 256){ float v = row[d]; ss += v*v; }
    ss = warpSum(ss);
    if ((threadIdx.x & 31) == 0) sred[threadIdx.x >> 5] = ss;
    __syncthreads();
    if (threadIdx.x == 0){
        float s = 0.f;
        #pragma unroll
        for (int i = 0; i < 8; i++) s += sred[i];
        sscale = rsqrtf(s*(1.f/D) + 1e-6f);
    }
    __syncthreads();
    float sc = sscale;
    for (int d = threadIdx.x; d < D; d += 256){
        float v = row[d]*sc*w[d];
        if (outF) outF[(long long)t*D + d] = v;
        if (outH) outH[(long long)t*D + d] = __float2half_rn(v);
    }
}

__global__ void router_kernel(const float* __restrict__ rw){
    int t = blockIdx.x;
    __shared__ float sm[8][4];
    float acc[4] = {0,0,0,0};
    for (int d = threadIdx.x; d < D; d += 256){
        float xv = g_xn[(long long)t*D + d];
        #pragma unroll
        for (int j = 0; j < 4; j++) acc[j] += xv*rw[j*D + d];
    }
    #pragma unroll
    for (int j = 0; j < 4; j++) acc[j] = warpSum(acc[j]);
    if ((threadIdx.x & 31) == 0){
        #pragma unroll
        for (int j = 0; j < 4; j++) sm[threadIdx.x >> 5][j] = acc[j];
    }
    __syncthreads();
    if (threadIdx.x == 0){
        float lg[4];
        #pragma unroll
        for (int j = 0; j < 4; j++){ float s = 0.f; for (int w2 = 0; w2 < 8; w2++) s += sm[w2][j]; lg[j] = s; }
        float mx = fmaxf(fmaxf(lg[0], lg[1]), fmaxf(lg[2], lg[3]));
        float sum = 0.f;
        #pragma unroll
        for (int j = 0; j < 4; j++){ lg[j] = __expf(lg[j] - mx); sum += lg[j]; }
        const float c[4] = {0.5f, 0.2f, 0.15f, 0.15f};
        float s2 = 0.f;
        #pragma unroll
        for (int j = 0; j < 4; j++){ lg[j] = lg[j]/sum*c[j]; s2 += lg[j]; }
        #pragma unroll
        for (int j = 0; j < 4; j++) g_weights[t*4 + j] = lg[j]/s2;
    }
}

__global__ void scan_kernel(const float* __restrict__ A_log, const float* __restrict__ Dp){
    int w = threadIdx.x >> 5, lane = threadIdx.x & 31;
    int d = blockIdx.x*4 + w;
    float4 A0;
    A0.x = -__expf(A_log[d*NS + lane*4 + 0]);
    A0.y = -__expf(A_log[d*NS + lane*4 + 1]);
    A0.z = -__expf(A_log[d*NS + lane*4 + 2]);
    A0.w = -__expf(A_log[d*NS + lane*4 + 3]);
    float Dpd = Dp[d];
    float4 h = make_float4(0.f,0.f,0.f,0.f);
    const __half2* __restrict__ P2 = (const __half2*)g_projH;
    for (int t = 0; t < L; t++){
        float2 b0 = __half22float2(P2[t*160 + 32 + lane*2]);
        float2 b1 = __half22float2(P2[t*160 + 32 + lane*2 + 1]);
        float2 c0 = __half22float2(P2[t*160 + 96 + lane*2]);
        float2 c1 = __half22float2(P2[t*160 + 96 + lane*2 + 1]);
        float ddt = __half2float(g_deltaH[t*D + d]);
        float xx  = __half2float(g_snselH[t*D + d]);
        float dx = ddt*xx;
        h.x = __expf(ddt*A0.x)*h.x + dx*b0.x;
        h.y = __expf(ddt*A0.y)*h.y + dx*b0.y;
        h.z = __expf(ddt*A0.z)*h.z + dx*b1.x;
        h.w = __expf(ddt*A0.w)*h.w + dx*b1.y;
        float acc = h.x*c0.x + h.y*c0.y + h.z*c1.x + h.w*c1.y;
        acc = warpSum(acc);
        if (lane == 0)
            g_pinH[t*D + d] = __float2half_rn(acc + g_xn[t*D + d]*Dpd);
    }
}

__global__ void qrope_kernel(const float* __restrict__ qn_w){
    int t = blockIdx.x;
    int h = threadIdx.x >> 5, l = threadIdx.x & 31;
    float a = __half2float(g_qkvH[(long long)t*QKVN + h*HD + l]);
    float b = __half2float(g_qkvH[(long long)t*QKVN + h*HD + l + 32]);
    float ss = warpSum(a*a + b*b);
    float sc = rsqrtf(ss*(1.f/HD) + 1e-6f) * 0.125f;
    a = a*sc*qn_w[l]; b = b*sc*qn_w[l+32];
    float inv = __expf(-(float)l*(1.f/32.f)*9.210340371976184f);
    float s, c; sincosf((float)t*inv, &s, &c);
    long long base = ((long long)h*L + t)*HD;
    g_qrH[base + l]      = __float2half_rn(a*c - b*s);
    g_qrH[base + l + 32] = __float2half_rn(b*c + a*s);
}

__global__ void kvrope_kernel(const float* __restrict__ kn_w){
    int t = blockIdx.x;
    int w = threadIdx.x >> 5, l = threadIdx.x & 31;
    if (w < 8){
        int j = w;
        float a = __half2float(g_qkvH[(long long)t*QKVN + 1024 + j*HD + l]);
        float b = __half2float(g_qkvH[(long long)t*QKVN + 1024 + j*HD + l + 32]);
        float ss = warpSum(a*a + b*b);
        float sc = rsqrtf(ss*(1.f/HD) + 1e-6f);
        a = a*sc*kn_w[l]; b = b*sc*kn_w[l+32];
        float inv = __expf(-(float)l*(1.f/32.f)*9.210340371976184f);
        float s, c; sincosf((float)t*inv, &s, &c);
        __half o1 = __float2half_rn(a*c - b*s);
        __half o2 = __float2half_rn(b*c + a*s);
        #pragma unroll
        for (int r = 0; r < 2; r++){
            long long base = ((long long)(2*j + r)*L + t)*HD;
            g_krH[base + l]      = o1;
            g_krH[base + l + 32] = o2;
        }
    } else {
        int j = w - 8;
        __half a = g_qkvH[(long long)t*QKVN + 1536 + j*HD + l];
        __half b = g_qkvH[(long long)t*QKVN + 1536 + j*HD + l + 32];
        #pragma unroll
        for (int r = 0; r < 2; r++){
            long long hb = (long long)(2*j + r)*HD;
            g_vtH[(hb + l)*L + t]      = a;
            g_vtH[(hb + l + 32)*L + t] = b;
        }
    }
}

__global__ void softmax_kernel(){
    __half* row = g_scoresH + (long long)blockIdx.x*L;
    __shared__ float sred[8];
    int tid = threadIdx.x;
    float mx = -1e30f;
    for (int i = tid; i < L; i += 256) mx = fmaxf(mx, __half2float(row[i]));
    #pragma unroll
    for (int o = 16; o; o >>= 1) mx = fmaxf(mx, __shfl_xor_sync(0xffffffffu, mx, o));
    if ((tid & 31) == 0) sred[tid >> 5] = mx;
    __syncthreads();
    if (tid == 0){ float m = sred[0]; for (int i = 1; i < 8; i++) m = fmaxf(m, sred[i]); sred[0] = m; }
    __syncthreads();
    mx = sred[0];
    __syncthreads();
    float s = 0.f;
    for (int i = tid; i < L; i += 256){
        float e = __expf(__half2float(row[i]) - mx);
        row[i] = __float2half_rn(e);
        s += e;
    }
    s = warpSum(s);
    if ((tid & 31) == 0) sred[tid >> 5] = s;
    __syncthreads();
    if (tid == 0){
        float t2 = 0.f;
        for (int i = 0; i < 8; i++) t2 += sred[i];
        g_sinv[blockIdx.x] = 1.f/t2;
    }
}

__global__ void conv_silu_kernel(const float* __restrict__ dww, const float* __restrict__ dwb){
    int t = blockIdx.x;
    for (int d = threadIdx.x; d < D; d += 256){
        float v = g_xn[(long long)t*D + d]*dww[d*3+1] + dwb[d];
        if (t > 0)     v += g_xn[(long long)(t-1)*D + d]*dww[d*3+0];
        if (t < L-1)   v += g_xn[(long long)(t+1)*D + d]*dww[d*3+2];
        g_pinH[2*L*D + (long long)t*D + d] = __float2half_rn(v/(1.f + __expf(-v)));
    }
}

__global__ void mix_kernel(const float* __restrict__ x, const float* __restrict__ mem){
    int t = blockIdx.x;
    float w0 = g_weights[t*4+0], w1 = g_weights[t*4+1];
    float w2 = g_weights[t*4+2], w3 = g_weights[t*4+3];
    for (int d = threadIdx.x; d < D; d += 256){
        long long i = (long long)t*D + d;
        float v = x[i] + w0*g_pout[i] + w1*g_pout[(long long)L*D + i]
                + w2*g_pout[2LL*L*D + i] + w3*mem[i];
        g_x2[i] = v;
        g_x2H[i] = __float2half_rn(v);
    }
}

__global__ void gate_kernel(const float* __restrict__ n2w, const float* __restrict__ gw){
    int t = blockIdx.x;
    __shared__ float sred[8];
    __shared__ float sacc[8][8];
    __shared__ float sscale;
    const float* row = g_x2 + (long long)t*D;
    float ss = 0.f;
    for (int d = threadIdx.x; d < D; d += 256){ float v = row[d]; ss += v*v; }
    ss = warpSum(ss);
    if ((threadIdx.x & 31) == 0) sred[threadIdx.x >> 5] = ss;
    __syncthreads();
    if (threadIdx.x == 0){
        float s = 0.f; for (int i = 0; i < 8; i++) s += sred[i];
        sscale = rsqrtf(s*(1.f/D) + 1e-6f);
    }
    __syncthreads();
    float sc = sscale;
    float acc[8] = {0,0,0,0,0,0,0,0};
    for (int d = threadIdx.x; d < D; d += 256){
        float xv = row[d]*sc*n2w[d];
        #pragma unroll
        for (int e = 0; e < 8; e++) acc[e] += xv*gw[e*D + d];
    }
    #pragma unroll
    for (int e = 0; e < 8; e++) acc[e] = warpSum(acc[e]);
    if ((threadIdx.x & 31) == 0){
        #pragma unroll
        for (int e = 0; e < 8; e++) sacc[threadIdx.x >> 5][e] = acc[e];
    }
    __syncthreads();
    if (threadIdx.x == 0){
        float lg[8];
        #pragma unroll
        for (int e = 0; e < 8; e++){ float s = 0.f; for (int w2 = 0; w2 < 8; w2++) s += sacc[w2][e]; lg[e] = s; }
        float v1 = -1e30f; int i1 = 0;
        for (int e = 0; e < 8; e++) if (lg[e] > v1){ v1 = lg[e]; i1 = e; }
        float v2 = -1e30f; int i2 = 0;
        for (int e = 0; e < 8; e++) if (e != i1 && lg[e] > v2){ v2 = lg[e]; i2 = e; }
        g_vals[t*2+0] = v1; g_vals[t*2+1] = v2;
        g_topidx[t*2+0] = i1; g_topidx[t*2+1] = i2;
    }
}

__global__ void colsoftmax_kernel(){
    int i = blockIdx.x;
    int t = threadIdx.x;
    __shared__ float red[32];
    float v = g_vals[t*2 + i];
    float m = v;
    #pragma unroll
    for (int o = 16; o; o >>= 1) m = fmaxf(m, __shfl_xor_sync(0xffffffffu, m, o));
    if ((t & 31) == 0) red[t >> 5] = m;
    __syncthreads();
    if (t == 0){ float mm = red[0]; for (int k = 1; k < 32; k++) mm = fmaxf(mm, red[k]); red[0] = mm; }
    __syncthreads();
    m = red[0];
    __syncthreads();
    float e = __expf(v - m);
    float s = e;
    #pragma unroll
    for (int o = 16; o; o >>= 1) s += __shfl_xor_sync(0xffffffffu, s, o);
    if ((t & 31) == 0) red[t >> 5] = s;
    __syncthreads();
    if (t == 0){ float sm = 0.f; for (int k = 0; k < 32; k++) sm += red[k]; red[0] = sm; }
    __syncthreads();
    float w = e / red[0];
    if (i == 0) g_w0[t] = w; else g_w1[t] = w;
}

__global__ void zero_cnt_kernel(){
    if (threadIdx.x < E) g_cnt[threadIdx.x] = 0;
}

__global__ void compact_kernel(){
    int t = blockIdx.x*256 + threadIdx.x;
    if (t >= L) return;
    #pragma unroll
    for (int i = 0; i < 2; i++){
        int e = g_topidx[t*2 + i];
        int p = atomicAdd(&g_cnt[e], 1);
        g_tok[e*L + p] = t;
        g_slot[e*L + p] = i;
    }
}

__global__ void final_kernel(float* __restrict__ out){
    int t = blockIdx.x;
    for (int d = threadIdx.x; d < D; d += 256){
        long long i = (long long)t*D + d;
        out[i] = g_x2[i] + 0.1f*(g_moe[i] + g_moe[(long long)L*D + i]);
    }
}

// ------------------ launch ------------------
namespace {
constexpr int SMEMH = NSTG*(128+64)*LDSH*2;  // 82944 bytes
inline dim3 grd(int M, int N, int Z){ return dim3(N/64, (M+127)/128, Z); }
inline int cgrid(long long n){ return (int)((n/4 + 255)/256); }
}

extern "C" void kernel_launch(void* const* d_in, const int* in_sizes, int n_in,
                              void* d_out, int out_size)
{
    const float* x         = (const float*)d_in[0];
    const float* mem       = (const float*)d_in[1];
    const float* norm1_w   = (const float*)d_in[2];
    const float* router_w  = (const float*)d_in[3];
    const float* ssm_norm_w= (const float*)d_in[4];
    const float* x_proj_w  = (const float*)d_in[5];
    const float* dt_proj_w = (const float*)d_in[6];
    const float* dt_proj_b = (const float*)d_in[7];
    const float* A_log     = (const float*)d_in[8];
    const float* D_param   = (const float*)d_in[9];
    const float* ssm_out_w = (const float*)d_in[10];
    const float* sel_w     = (const float*)d_in[11];
    const float* sel_b     = (const float*)d_in[12];
    const float* sel_gate  = (const float*)d_in[13];
    const float* q_w       = (const float*)d_in[14];
    const float* k_w       = (const float*)d_in[15];
    const float* v_w       = (const float*)d_in[16];
    const float* o_w       = (const float*)d_in[17];
    const float* qn_w      = (const float*)d_in[18];
    const float* kn_w      = (const float*)d_in[19];
    const float* dw_w      = (const float*)d_in[20];
    const float* dw_b      = (const float*)d_in[21];
    const float* pw_w      = (const float*)d_in[22];
    const float* pw_b      = (const float*)d_in[23];
    const float* norm2_w   = (const float*)d_in[24];
    const float* gate_w    = (const float*)d_in[25];
    const float* e_w1      = (const float*)d_in[26];
    const float* e_w2      = (const float*)d_in[27];
    const float* e_lw      = (const float*)d_in[28];
    const float* e_lb      = (const float*)d_in[29];
    float* out = (float*)d_out;

    float *p_xn, *p_pout, *p_sinv, *p_x2;
    __half *p_xnH, *p_snH, *p_snselH, *p_projH, *p_deltaH, *p_pinH;
    __half *p_wqkvH, *p_qkvH, *p_qrH, *p_krH, *p_vtH, *p_scoresH;
    __half *p_x2H, *p_hhH, *p_yH;
    __half *p_selwH, *p_xpwH, *p_dtwH, *p_wprojH, *p_ew1H, *p_ew2H, *p_elwH;
    cudaGetSymbolAddress((void**)&p_xn, g_xn);
    cudaGetSymbolAddress((void**)&p_xnH, g_xnH);
    cudaGetSymbolAddress((void**)&p_snH, g_snH);
    cudaGetSymbolAddress((void**)&p_snselH, g_snselH);
    cudaGetSymbolAddress((void**)&p_projH, g_projH);
    cudaGetSymbolAddress((void**)&p_deltaH, g_deltaH);
    cudaGetSymbolAddress((void**)&p_pinH, g_pinH);
    cudaGetSymbolAddress((void**)&p_pout, g_pout);
    cudaGetSymbolAddress((void**)&p_wqkvH, g_wqkvH);
    cudaGetSymbolAddress((void**)&p_qkvH, g_qkvH);
    cudaGetSymbolAddress((void**)&p_qrH, g_qrH);
    cudaGetSymbolAddress((void**)&p_krH, g_krH);
    cudaGetSymbolAddress((void**)&p_vtH, g_vtH);
    cudaGetSymbolAddress((void**)&p_scoresH, g_scoresH);
    cudaGetSymbolAddress((void**)&p_sinv, g_sinv);
    cudaGetSymbolAddress((void**)&p_x2, g_x2);
    cudaGetSymbolAddress((void**)&p_x2H, g_x2H);
    cudaGetSymbolAddress((void**)&p_hhH, g_hhH);
    cudaGetSymbolAddress((void**)&p_yH, g_yH);
    cudaGetSymbolAddress((void**)&p_selwH, g_selwH);
    cudaGetSymbolAddress((void**)&p_xpwH, g_xpwH);
    cudaGetSymbolAddress((void**)&p_dtwH, g_dtwH);
    cudaGetSymbolAddress((void**)&p_wprojH, g_wprojH);
    cudaGetSymbolAddress((void**)&p_ew1H, g_ew1H);
    cudaGetSymbolAddress((void**)&p_ew2H, g_ew2H);
    cudaGetSymbolAddress((void**)&p_elwH, g_elwH);

    #define SETSM(KER) cudaFuncSetAttribute((const void*)&KER, cudaFuncAttributeMaxDynamicSharedMemorySize, SMEMH)
    SETSM((gemm_h<3,false,true>));
    SETSM((gemm_h<0,false,true>));
    SETSM((gemm_h<2,false,true>));
    SETSM((gemm_h<7,false,false>));
    SETSM((gemm_h<6,false,true>));
    SETSM((gemm_h<4,true,true>));
    SETSM((gemm_h<5,false,false>));
    #undef SETSM

    // 0. weight conversions: merged small set + big expert sets
    {
        long long n0 = (long long)D*D, n1 = (long long)PRJ*D, n2 = (long long)D*DT;
        long long tot = n0*4 + n1 + n2;
        f2h6_kernel<<<cgrid(tot), 256>>>(
            sel_w, p_selwH, n0,
            x_proj_w, p_xpwH, n1,
            dt_proj_w, p_dtwH, n2,
            ssm_out_w, p_wprojH, n0,
            o_w, p_wprojH + (long long)D*D, n0,
            pw_w, p_wprojH + 2LL*D*D, n0);
    }
    f2h_w1_kernel<<<E*2*HID, 256>>>(e_w1, p_ew1H);
    f2h_kernel<<<cgrid((long long)E*D*HID), 256>>>(e_w2, p_ew2H, (long long)E*D*HID);
    f2h_kernel<<<cgrid((long long)E*D*D), 256>>>(e_lw, p_elwH, (long long)E*D*D);
    packqkv_kernel<<<QKVN, 256>>>(q_w, k_w, v_w);

    // 1. xn = rms(x); router; conv (slice2) early
    rms_kernel<<<L, 256>>>(x, norm1_w, p_xn, p_xnH);
    router_kernel<<<L, 256>>>(router_w);
    conv_silu_kernel<<<L, 256>>>(dw_w, dw_b);
    // 2. sn = rms(xn)
    rms_kernel<<<L, 256>>>(p_xn, ssm_norm_w, nullptr, p_snH);
    // 3. sn_sel
    gemm_h<3,false,true><<<grd(L, D, 1), 256, SMEMH>>>(p_snH, p_selwH, p_snselH,
        L, D, D, D, D, D, 0, 0, 0, sel_b, p_snH, sel_gate, -1);
    // 4. proj
    gemm_h<0,false,true><<<grd(L, PRJ, 1), 256, SMEMH>>>(p_snselH, p_xpwH, p_projH,
        L, PRJ, D, D, D, PRJ, 0, 0, 0, nullptr, nullptr, nullptr, -1);
    // 5. delta
    gemm_h<2,false,true><<<grd(L, D, 1), 256, SMEMH>>>(p_projH, p_dtwH, p_deltaH,
        L, D, DT, PRJ, DT, D, 0, 0, 0, dt_proj_b, nullptr, nullptr, -1);
    // 6. scan (writes slice0 of pinH)
    scan_kernel<<<D/4, 128>>>(A_log, D_param);
    // 7. fused qkv
    gemm_h<0,false,true><<<grd(L, QKVN, 1), 256, SMEMH>>>(p_xnH, p_wqkvH, p_qkvH,
        L, QKVN, D, D, D, QKVN, 0, 0, 0, nullptr, nullptr, nullptr, -1);
    // 8. rope
    qrope_kernel<<<L, 512>>>(qn_w);
    kvrope_kernel<<<L, 512>>>(kn_w);
    // 9. scores
    gemm_h<0,false,true><<<grd(L, L, H), 256, SMEMH>>>(p_qrH, p_krH, p_scoresH,
        L, L, HD, HD, HD, L,
        (long long)L*HD, (long long)L*HD, (long long)L*L, nullptr, nullptr, nullptr, -1);
    // 10. softmax
    softmax_kernel<<<H*L, 256>>>();
    // 11. attn@v -> slice1 of pinH
    gemm_h<6,false,true><<<grd(L, HD, H), 256, SMEMH>>>(p_scoresH, p_vtH, p_pinH + (long long)L*D,
        L, HD, L, L, L, D,
        (long long)L*L, (long long)HD*L, (long long)HD, p_sinv, nullptr, nullptr, -1);
    // 12. batched output projections (ssm_out | o_w | pw), z=3
    gemm_h<7,false,false><<<grd(L, D, 3), 256, SMEMH>>>(p_pinH, p_wprojH, p_pout,
        L, D, D, D, D, D,
        (long long)L*D, (long long)D*D, (long long)L*D, pw_b, nullptr, nullptr, -1);
    // 13. mix
    mix_kernel<<<L, 256>>>(x, mem);
    // 14. gate + top2 + seq softmax + compaction
    gate_kernel<<<L, 256>>>(norm2_w, gate_w);
    colsoftmax_kernel<<<2, 1024>>>();
    zero_cnt_kernel<<<1, 32>>>();
    compact_kernel<<<(L+255)/256, 256>>>();
    // 15. routed experts — w1 with fused SwiGLU epilogue
    gemm_h<4,true,true><<<grd(L, 2*HID, E), 256, SMEMH>>>(p_x2H, p_ew1H, p_hhH,
        L, 2*HID, D, D, D, HID,
        0, (long long)2*HID*D, (long long)L*HID, nullptr, nullptr, nullptr, -2);
    gemm_h<0,false,true><<<grd(L, D, E), 256, SMEMH>>>(p_hhH, p_ew2H, p_yH,
        L, D, HID, HID, HID, D,
        (long long)L*HID, (long long)D*HID, (long long)L*D, nullptr, nullptr, nullptr, -2);
    gemm_h<5,false,false><<<grd(L, D, E), 256, SMEMH>>>(p_yH, p_elwH, nullptr,
        L, D, D, D, D, D,
        (long long)L*D, (long long)D*D, 0, e_lb, nullptr, nullptr, -2);
    // 16. final
    final_kernel<<<L, 256>>>(out);
}